// round 5
// baseline (speedup 1.0000x reference)
#include <cuda_runtime.h>
#include <math.h>
#include <stdint.h>

#define BSZ 4096
#define DSZ 512

// Small scratch globals (no dynamic allocation anywhere).
__device__ float  g_xt[3][BSZ];        // time components per feature set
__device__ int    g_lab[BSZ];          // labels
__device__ float  g_cnt[BSZ];          // per-index label match count
__device__ float  g_se_row[3][BSZ];    // sum(exp(logit)) over cols, per pair
__device__ float  g_se_col[3][BSZ];    // sum(exp(logit)) over rows, per pair
__device__ double g_matched_t[3];      // sum of t=log2(u) over label-matched pairs
__device__ double g_acc_entail;

// ---------------------------------------------------------------------------
// init: zero accumulators, copy labels (int32 — JAX x64 is disabled, so the
// reference's jnp.int64 silently becomes int32)
// ---------------------------------------------------------------------------
__global__ void init_kernel(const int* __restrict__ labels) {
    const int t = blockIdx.x * blockDim.x + threadIdx.x;
    if (t < 3 * BSZ) {
        ((float*)g_se_row)[t] = 0.0f;
        ((float*)g_se_col)[t] = 0.0f;
    }
    if (t < BSZ) g_lab[t] = labels[t];
    if (t < 3)   g_matched_t[t] = 0.0;
    if (t == 0)  g_acc_entail = 0.0;
}

// ---------------------------------------------------------------------------
// per-index label match counts: cnt_i = #{j : lab_j == lab_i}
// ---------------------------------------------------------------------------
__global__ void __launch_bounds__(256)
cnt_kernel() {
    __shared__ int sl[BSZ];
    const int tid = threadIdx.x;
    for (int t = tid; t < BSZ; t += 256) sl[t] = g_lab[t];
    __syncthreads();
    const int i  = blockIdx.x * 256 + tid;
    const int li = sl[i];
    int c = 0;
#pragma unroll 8
    for (int j = 0; j < BSZ; j++) c += (sl[j] == li) ? 1 : 0;
    g_cnt[i] = (float)c;
}

// ---------------------------------------------------------------------------
// time component: xt[i] = sqrt(1/curv + ||f_i||^2); one block per row
// ---------------------------------------------------------------------------
__global__ void time_kernel(const float* __restrict__ f,
                            const float* __restrict__ pCurv, int idx) {
    __shared__ float red[128];
    const int i   = blockIdx.x;
    const int tid = threadIdx.x;
    const float4 v = ((const float4*)(f + (size_t)i * DSZ))[tid];
    float s = v.x * v.x + v.y * v.y + v.z * v.z + v.w * v.w;
    red[tid] = s;
    __syncthreads();
    for (int o = 64; o > 0; o >>= 1) {
        if (tid < o) red[tid] += red[tid + o];
        __syncthreads();
    }
    if (tid == 0) g_xt[idx][i] = sqrtf(1.0f / (*pCurv) + red[0]);
}

// ---------------------------------------------------------------------------
// entailment: fa = dna (set 1), fb = image (set 0); one block per row
// ---------------------------------------------------------------------------
__global__ void entail_kernel(const float* __restrict__ dna,
                              const float* __restrict__ img,
                              const float* __restrict__ pCurv) {
    __shared__ float redd[128];
    __shared__ float redn[128];
    const int i   = blockIdx.x;
    const int tid = threadIdx.x;
    const float4 xv = ((const float4*)(dna + (size_t)i * DSZ))[tid];
    const float4 yv = ((const float4*)(img + (size_t)i * DSZ))[tid];
    float d = xv.x * yv.x + xv.y * yv.y + xv.z * yv.z + xv.w * yv.w;
    float n = xv.x * xv.x + xv.y * xv.y + xv.z * xv.z + xv.w * xv.w;
    redd[tid] = d; redn[tid] = n;
    __syncthreads();
    for (int o = 64; o > 0; o >>= 1) {
        if (tid < o) { redd[tid] += redd[tid + o]; redn[tid] += redn[tid + o]; }
        __syncthreads();
    }
    if (tid == 0) {
        const float curv  = *pCurv;
        const float xt    = g_xt[1][i];     // dna time
        const float yt    = g_xt[0][i];     // image time
        const float dot   = redd[0];
        const float normx = sqrtf(redn[0]);
        const float c     = curv * (dot - xt * yt);       // <= -1
        const float num   = yt + c * xt;
        const float den   = normx * sqrtf(fmaxf(c * c - 1.0f, 0.0f));
        float ain = num / (den + 1e-8f);
        ain = fminf(fmaxf(ain, -1.0f + 1e-8f), 1.0f - 1e-8f);
        const float ang = acosf(ain);
        float asin_in = 0.2f / (normx * sqrtf(curv) + 1e-6f);
        asin_in = fminf(fmaxf(asin_in, -1.0f + 1e-6f), 1.0f - 1e-6f);
        const float ap = asinf(asin_in);
        atomicAdd(&g_acc_entail, (double)fmaxf(ang - ap, 0.0f));
    }
}

// ---------------------------------------------------------------------------
// fused GEMM + hyperbolic logits + in-tile CE accumulation.
// logit g_ij = scale * ln(u),  u = c + sqrt(c^2-1),  c = clip(-curv*(dot - xt*yt))
// e_ij = exp(g_ij) = u^scale = exp2(scale * log2(u));  logits <= 0 so no max
// subtraction is needed (exp in [~1e-32, 1], representable in fp32).
// Accumulate row sums -> g_se_row[pair], col sums -> g_se_col[pair],
// matched t=log2(u) -> g_matched_t[pair].
// 128x128 tile, BK=16, 256 threads, 8x8 per thread.
// ---------------------------------------------------------------------------
__global__ void __launch_bounds__(256, 2)
gemm_ce(const float* __restrict__ A, const float* __restrict__ Bm,
        int ia, int ib, int pair,
        const float* __restrict__ pLS, const float* __restrict__ pCurv) {
    __shared__ float As[16][132];
    __shared__ float Bs[16][132];
    __shared__ int   labA[128];
    __shared__ int   labB[128];
    __shared__ float mred[8];

    const int tid = threadIdx.x;
    const int bx  = blockIdx.x;   // col block
    const int by  = blockIdx.y;   // row block
    const int tr  = (tid >> 4) * 8;
    const int tc  = (tid & 15) * 8;

    if (tid < 128) {
        labA[tid] = g_lab[by * 128 + tid];
        labB[tid] = g_lab[bx * 128 + tid];
    }

    const int l0 = tid, l1 = tid + 256;
    const int m0 = l0 >> 2, k0 = (l0 & 3) * 4;
    const int m1 = l1 >> 2, k1 = (l1 & 3) * 4;
    const float* Ar0 = A  + (size_t)(by * 128 + m0) * DSZ + k0;
    const float* Ar1 = A  + (size_t)(by * 128 + m1) * DSZ + k1;
    const float* Br0 = Bm + (size_t)(bx * 128 + m0) * DSZ + k0;
    const float* Br1 = Bm + (size_t)(bx * 128 + m1) * DSZ + k1;

    float acc[8][8];
#pragma unroll
    for (int i = 0; i < 8; i++)
#pragma unroll
        for (int j = 0; j < 8; j++) acc[i][j] = 0.0f;

    for (int kb = 0; kb < DSZ; kb += 16) {
        const float4 a0 = *(const float4*)(Ar0 + kb);
        const float4 a1 = *(const float4*)(Ar1 + kb);
        const float4 b0 = *(const float4*)(Br0 + kb);
        const float4 b1 = *(const float4*)(Br1 + kb);
        __syncthreads();
        As[k0 + 0][m0] = a0.x; As[k0 + 1][m0] = a0.y; As[k0 + 2][m0] = a0.z; As[k0 + 3][m0] = a0.w;
        As[k1 + 0][m1] = a1.x; As[k1 + 1][m1] = a1.y; As[k1 + 2][m1] = a1.z; As[k1 + 3][m1] = a1.w;
        Bs[k0 + 0][m0] = b0.x; Bs[k0 + 1][m0] = b0.y; Bs[k0 + 2][m0] = b0.z; Bs[k0 + 3][m0] = b0.w;
        Bs[k1 + 0][m1] = b1.x; Bs[k1 + 1][m1] = b1.y; Bs[k1 + 2][m1] = b1.z; Bs[k1 + 3][m1] = b1.w;
        __syncthreads();
#pragma unroll
        for (int k = 0; k < 16; k++) {
            float a_reg[8], b_reg[8];
            *(float4*)(a_reg)     = *(const float4*)&As[k][tr];
            *(float4*)(a_reg + 4) = *(const float4*)&As[k][tr + 4];
            *(float4*)(b_reg)     = *(const float4*)&Bs[k][tc];
            *(float4*)(b_reg + 4) = *(const float4*)&Bs[k][tc + 4];
#pragma unroll
            for (int i = 0; i < 8; i++)
#pragma unroll
                for (int j = 0; j < 8; j++)
                    acc[i][j] += a_reg[i] * b_reg[j];
        }
    }

    // ---- epilogue: logits -> exp sums + matched sum ----
    const float ls    = *pLS;
    const float curv  = *pCurv;
    const float scale = -ls / sqrtf(curv);   // exponent: e = u^scale
    const float lo    = 1.0f + 1e-8f;

    float xai[8], xbj[8];
    int   lai[8], lbj[8];
#pragma unroll
    for (int i = 0; i < 8; i++) {
        xai[i] = g_xt[ia][by * 128 + tr + i];
        lai[i] = labA[tr + i];
    }
#pragma unroll
    for (int j = 0; j < 8; j++) {
        xbj[j] = g_xt[ib][bx * 128 + tc + j];
        lbj[j] = labB[tc + j];
    }

    float erow[8], ecol[8];
#pragma unroll
    for (int i = 0; i < 8; i++) { erow[i] = 0.0f; ecol[i] = 0.0f; }
    float msum = 0.0f;

#pragma unroll
    for (int i = 0; i < 8; i++) {
#pragma unroll
        for (int j = 0; j < 8; j++) {
            float c = -curv * (acc[i][j] - xai[i] * xbj[j]);
            c = fmaxf(c, lo);
            const float u = c + sqrtf(fmaf(c, c, -1.0f));
            const float t = __log2f(u);                 // acosh(c)/ln2
            const float e = exp2f(scale * t);           // exp(logit), logit<=0
            erow[i] += e;
            ecol[j] += e;
            if (lai[i] == lbj[j]) msum += t;
        }
    }

    // row sums: reduce across 16 lanes sharing a row group (same tid>>4)
#pragma unroll
    for (int i = 0; i < 8; i++) {
        float v = erow[i];
        v += __shfl_down_sync(0xffffffffu, v, 8, 16);
        v += __shfl_down_sync(0xffffffffu, v, 4, 16);
        v += __shfl_down_sync(0xffffffffu, v, 2, 16);
        v += __shfl_down_sync(0xffffffffu, v, 1, 16);
        if ((tid & 15) == 0)
            atomicAdd(&g_se_row[pair][by * 128 + tr + i], v);
    }

    // col sums: stage per-rowgroup partials in smem (reuse As), then reduce
    __syncthreads();                       // everyone done reading As
    float* s = &As[0][0];                  // [16][132] layout, stride 132
#pragma unroll
    for (int j = 0; j < 8; j++)
        s[(tid >> 4) * 132 + tc + j] = ecol[j];

    // matched: warp reduce, stage per-warp
    for (int o = 16; o > 0; o >>= 1)
        msum += __shfl_down_sync(0xffffffffu, msum, o);
    if ((tid & 31) == 0) mred[tid >> 5] = msum;
    __syncthreads();

    if (tid < 128) {
        float v = 0.0f;
#pragma unroll
        for (int r = 0; r < 16; r++) v += s[r * 132 + tid];
        atomicAdd(&g_se_col[pair][bx * 128 + tid], v);
    }
    if (tid == 0) {
        float tot = 0.0f;
#pragma unroll
        for (int w = 0; w < 8; w++) tot += mred[w];
        atomicAdd(&g_matched_t[pair], (double)tot);
    }
}

// ---------------------------------------------------------------------------
// finalize: contrast = [ sum_i cnt_i*(lse_row + lse_col over 3 pairs)
//                        - 2*scale*ln2*sum_p matched_t_p ] / (6*B)
// ---------------------------------------------------------------------------
__global__ void __launch_bounds__(256)
finalize_kernel(const float* __restrict__ pLS, const float* __restrict__ pCurv,
                float* __restrict__ out, int out_size) {
    __shared__ double red[256];
    const int tid = threadIdx.x;
    double acc = 0.0;
    for (int i = tid; i < BSZ; i += 256) {
        const double c = (double)g_cnt[i];
        double l = 0.0;
#pragma unroll
        for (int p = 0; p < 3; p++)
            l += (double)logf(g_se_row[p][i]) + (double)logf(g_se_col[p][i]);
        acc += c * l;
    }
    red[tid] = acc;
    __syncthreads();
    for (int o = 128; o > 0; o >>= 1) {
        if (tid < o) red[tid] += red[tid + o];
        __syncthreads();
    }
    if (tid == 0) {
        const double ls    = (double)(*pLS);
        const double curv  = (double)(*pCurv);
        const double scaleLn2 = -(ls / sqrt(curv)) * 0.6931471805599453;
        double matched = 0.0;
        for (int p = 0; p < 3; p++) matched += g_matched_t[p];
        matched *= scaleLn2;
        const double contrast = (red[0] - 2.0 * matched) / (6.0 * (double)BSZ);
        const double entail   = g_acc_entail / (double)BSZ;
        const double total    = contrast + 0.2 * entail;
        if (out_size > 0) out[0] = (float)total;
        if (out_size > 1) out[1] = (float)contrast;
        if (out_size > 2) out[2] = (float)entail;
    }
}

// ---------------------------------------------------------------------------
extern "C" void kernel_launch(void* const* d_in, const int* in_sizes, int n_in,
                              void* d_out, int out_size) {
    const float* img    = (const float*)d_in[0];
    const float* dna    = (const float*)d_in[1];
    const float* txt    = (const float*)d_in[2];
    const int*   labels = (const int*)d_in[3];   // int32! (JAX x64 disabled)
    const float* pLS    = (const float*)d_in[4];
    const float* pCurv  = (const float*)d_in[5];
    float*       out    = (float*)d_out;

    init_kernel<<<48, 256>>>(labels);
    cnt_kernel<<<BSZ / 256, 256>>>();
    time_kernel<<<BSZ, 128>>>(img, pCurv, 0);
    time_kernel<<<BSZ, 128>>>(dna, pCurv, 1);
    time_kernel<<<BSZ, 128>>>(txt, pCurv, 2);
    entail_kernel<<<BSZ, 128>>>(dna, img, pCurv);

    const float* feats[3] = {img, dna, txt};
    const int pa[3] = {0, 0, 1};
    const int pb[3] = {1, 2, 2};
    for (int p = 0; p < 3; p++) {
        gemm_ce<<<dim3(32, 32), 256>>>(feats[pa[p]], feats[pb[p]],
                                       pa[p], pb[p], p, pLS, pCurv);
    }
    finalize_kernel<<<1, 256>>>(pLS, pCurv, out, out_size);
}

// round 7
// speedup vs baseline: 1.6365x; 1.6365x over previous
#include <cuda_runtime.h>
#include <cuda_bf16.h>
#include <math.h>
#include <stdint.h>

#define BSZ 4096
#define DSZ 512

// ---------------------------------------------------------------------------
// scratch globals (no dynamic allocation anywhere)
// ---------------------------------------------------------------------------
__device__ __align__(16) __nv_bfloat16 g_hi[3][(size_t)BSZ * DSZ];  // 12 MB
__device__ __align__(16) __nv_bfloat16 g_lo[3][(size_t)BSZ * DSZ];  // 12 MB
__device__ float  g_xt[3][BSZ];
__device__ int    g_lab[BSZ];
__device__ float  g_cnt[BSZ];
__device__ float  g_se_row[3][BSZ];
__device__ float  g_se_col[3][BSZ];
__device__ double g_matched_t[3];
__device__ double g_acc_entail;

// ---------------------------------------------------------------------------
// PTX helpers — baseline ISA only (no sm_103a-gated instructions!)
// ---------------------------------------------------------------------------
__device__ __forceinline__ uint32_t smem_u32(const void* p) {
    uint32_t a;
    asm("{ .reg .u64 t; cvta.to.shared.u64 t, %1; cvt.u32.u64 %0, t; }"
        : "=r"(a) : "l"(p));
    return a;
}

__device__ __forceinline__ void cp16(uint32_t s, const void* g) {
    asm volatile("cp.async.cg.shared.global [%0], [%1], 16;"
                 :: "r"(s), "l"(g) : "memory");
}
#define CP_COMMIT() asm volatile("cp.async.commit_group;" ::: "memory")
#define CP_WAIT(n)  asm volatile("cp.async.wait_group %0;" :: "n"(n) : "memory")

__device__ __forceinline__ void ldsm4(uint32_t* r, uint32_t a) {
    asm volatile("ldmatrix.sync.aligned.m8n8.x4.shared.b16 {%0,%1,%2,%3}, [%4];"
                 : "=r"(r[0]), "=r"(r[1]), "=r"(r[2]), "=r"(r[3]) : "r"(a));
}

__device__ __forceinline__ void mma_bf16(float* c, const uint32_t* a,
                                         uint32_t b0, uint32_t b1) {
    asm volatile(
        "mma.sync.aligned.m16n8k16.row.col.f32.bf16.bf16.f32 "
        "{%0,%1,%2,%3}, {%4,%5,%6,%7}, {%8,%9}, {%0,%1,%2,%3};"
        : "+f"(c[0]), "+f"(c[1]), "+f"(c[2]), "+f"(c[3])
        : "r"(a[0]), "r"(a[1]), "r"(a[2]), "r"(a[3]), "r"(b0), "r"(b1));
}

// ---------------------------------------------------------------------------
// init: zero accumulators, copy labels (int32 — JAX x64 disabled)
// ---------------------------------------------------------------------------
__global__ void init_kernel(const int* __restrict__ labels) {
    const int t = blockIdx.x * blockDim.x + threadIdx.x;
    if (t < 3 * BSZ) {
        ((float*)g_se_row)[t] = 0.0f;
        ((float*)g_se_col)[t] = 0.0f;
    }
    if (t < BSZ) g_lab[t] = labels[t];
    if (t < 3)   g_matched_t[t] = 0.0;
    if (t == 0)  g_acc_entail = 0.0;
}

// ---------------------------------------------------------------------------
// split fp32 features into bf16 hi/lo
// ---------------------------------------------------------------------------
__global__ void __launch_bounds__(256)
split_kernel(const float* __restrict__ f, int set) {
    const int i = blockIdx.x * 256 + threadIdx.x;   // float4 index
    const float4 v = ((const float4*)f)[i];
    __nv_bfloat16 h0 = __float2bfloat16(v.x);
    __nv_bfloat16 h1 = __float2bfloat16(v.y);
    __nv_bfloat16 h2 = __float2bfloat16(v.z);
    __nv_bfloat16 h3 = __float2bfloat16(v.w);
    __nv_bfloat16 l0 = __float2bfloat16(v.x - __bfloat162float(h0));
    __nv_bfloat16 l1 = __float2bfloat16(v.y - __bfloat162float(h1));
    __nv_bfloat16 l2 = __float2bfloat16(v.z - __bfloat162float(h2));
    __nv_bfloat16 l3 = __float2bfloat16(v.w - __bfloat162float(h3));
    __nv_bfloat162* dh = (__nv_bfloat162*)(g_hi[set]) + (size_t)i * 2;
    __nv_bfloat162* dl = (__nv_bfloat162*)(g_lo[set]) + (size_t)i * 2;
    dh[0] = __halves2bfloat162(h0, h1);
    dh[1] = __halves2bfloat162(h2, h3);
    dl[0] = __halves2bfloat162(l0, l1);
    dl[1] = __halves2bfloat162(l2, l3);
}

// ---------------------------------------------------------------------------
// per-index label match counts
// ---------------------------------------------------------------------------
__global__ void __launch_bounds__(256)
cnt_kernel() {
    __shared__ int sl[BSZ];
    const int tid = threadIdx.x;
    for (int t = tid; t < BSZ; t += 256) sl[t] = g_lab[t];
    __syncthreads();
    const int i  = blockIdx.x * 256 + tid;
    const int li = sl[i];
    int c = 0;
#pragma unroll 8
    for (int j = 0; j < BSZ; j++) c += (sl[j] == li) ? 1 : 0;
    g_cnt[i] = (float)c;
}

// ---------------------------------------------------------------------------
// time component
// ---------------------------------------------------------------------------
__global__ void time_kernel(const float* __restrict__ f,
                            const float* __restrict__ pCurv, int idx) {
    __shared__ float red[128];
    const int i   = blockIdx.x;
    const int tid = threadIdx.x;
    const float4 v = ((const float4*)(f + (size_t)i * DSZ))[tid];
    float s = v.x * v.x + v.y * v.y + v.z * v.z + v.w * v.w;
    red[tid] = s;
    __syncthreads();
    for (int o = 64; o > 0; o >>= 1) {
        if (tid < o) red[tid] += red[tid + o];
        __syncthreads();
    }
    if (tid == 0) g_xt[idx][i] = sqrtf(1.0f / (*pCurv) + red[0]);
}

// ---------------------------------------------------------------------------
// entailment (dna -> image)
// ---------------------------------------------------------------------------
__global__ void entail_kernel(const float* __restrict__ dna,
                              const float* __restrict__ img,
                              const float* __restrict__ pCurv) {
    __shared__ float redd[128];
    __shared__ float redn[128];
    const int i   = blockIdx.x;
    const int tid = threadIdx.x;
    const float4 xv = ((const float4*)(dna + (size_t)i * DSZ))[tid];
    const float4 yv = ((const float4*)(img + (size_t)i * DSZ))[tid];
    float d = xv.x * yv.x + xv.y * yv.y + xv.z * yv.z + xv.w * yv.w;
    float n = xv.x * xv.x + xv.y * xv.y + xv.z * xv.z + xv.w * xv.w;
    redd[tid] = d; redn[tid] = n;
    __syncthreads();
    for (int o = 64; o > 0; o >>= 1) {
        if (tid < o) { redd[tid] += redd[tid + o]; redn[tid] += redn[tid + o]; }
        __syncthreads();
    }
    if (tid == 0) {
        const float curv  = *pCurv;
        const float xt    = g_xt[1][i];
        const float yt    = g_xt[0][i];
        const float dot   = redd[0];
        const float normx = sqrtf(redn[0]);
        const float c     = curv * (dot - xt * yt);
        const float num   = yt + c * xt;
        const float den   = normx * sqrtf(fmaxf(c * c - 1.0f, 0.0f));
        float ain = num / (den + 1e-8f);
        ain = fminf(fmaxf(ain, -1.0f + 1e-8f), 1.0f - 1e-8f);
        const float ang = acosf(ain);
        float asin_in = 0.2f / (normx * sqrtf(curv) + 1e-6f);
        asin_in = fminf(fmaxf(asin_in, -1.0f + 1e-6f), 1.0f - 1e-6f);
        const float ap = asinf(asin_in);
        atomicAdd(&g_acc_entail, (double)fmaxf(ang - ap, 0.0f));
    }
}

// ---------------------------------------------------------------------------
// warp-MMA GEMM (bf16 hi/lo, 3-term, mma.sync m16n8k16) + fused CE epilogue.
// Tile 128x128, BK=64, double-buffered cp.async, accumulators in registers.
//
// SMEM stage layout (row stride 144B = 128B data + 16B pad, conflict-free
// for ldmatrix): Ahi @0, Alo @18432, Bhi @36864, Blo @55296; stage=73728.
// stage0 @0, stage1 @73728, control @147456.
// ---------------------------------------------------------------------------
#define STG   73728
#define MOFS  18432
#define CTRL  147456
#define GEMM_SMEM (CTRL + 3200)

__device__ __forceinline__ void issue_chunk(
    uint32_t sstage,
    const __nv_bfloat16* __restrict__ Ah, const __nv_bfloat16* __restrict__ Al,
    const __nv_bfloat16* __restrict__ Bh, const __nv_bfloat16* __restrict__ Bl,
    int kchunk, int tid)
{
    const int col0 = kchunk * 64;
    const __nv_bfloat16* mats[4] = {Ah, Al, Bh, Bl};
#pragma unroll
    for (int m = 0; m < 4; m++) {
        const __nv_bfloat16* src = mats[m];
        const uint32_t sm = sstage + m * MOFS;
#pragma unroll
        for (int it = 0; it < 4; it++) {
            const int idx = tid + it * 256;
            const int row = idx >> 3;
            const int seg = idx & 7;
            cp16(sm + row * 144 + seg * 16,
                 src + (size_t)row * DSZ + col0 + seg * 8);
        }
    }
}

__global__ void __launch_bounds__(256, 1)
gemm_ce_wm(const float* __restrict__ pLS, const float* __restrict__ pCurv) {
    extern __shared__ char smem[];
    const int tid  = threadIdx.x;
    const int lane = tid & 31;
    const int wid  = tid >> 5;
    const int warp_m = wid & 3;     // 4 row groups of 32
    const int warp_n = wid >> 2;    // 2 col groups of 64
    const int bx = blockIdx.x, by = blockIdx.y, pair = blockIdx.z;
    const int PA[3] = {0, 0, 1};
    const int PB[3] = {1, 2, 2};
    const int ia = PA[pair], ib = PB[pair];

    const uint32_t sb = smem_u32(smem);

    float* xtA_s  = (float*)(smem + CTRL);
    float* xtB_s  = (float*)(smem + CTRL + 512);
    int*   labA_s = (int*)  (smem + CTRL + 1024);
    int*   labB_s = (int*)  (smem + CTRL + 1536);
    float* erow_s = (float*)(smem + CTRL + 2048);
    float* ecol_s = (float*)(smem + CTRL + 2560);
    float* msum_s = (float*)(smem + CTRL + 3072);

    const __nv_bfloat16* Ah = g_hi[ia] + (size_t)(by * 128) * DSZ;
    const __nv_bfloat16* Al = g_lo[ia] + (size_t)(by * 128) * DSZ;
    const __nv_bfloat16* Bh = g_hi[ib] + (size_t)(bx * 128) * DSZ;
    const __nv_bfloat16* Bl = g_lo[ib] + (size_t)(bx * 128) * DSZ;

    if (tid < 128) {
        xtA_s[tid]  = g_xt[ia][by * 128 + tid];
        xtB_s[tid]  = g_xt[ib][bx * 128 + tid];
        labA_s[tid] = g_lab[by * 128 + tid];
        labB_s[tid] = g_lab[bx * 128 + tid];
        erow_s[tid] = 0.0f;
        ecol_s[tid] = 0.0f;
    }
    if (tid == 0) *msum_s = 0.0f;

    float acc[2][8][4];
#pragma unroll
    for (int mi = 0; mi < 2; mi++)
#pragma unroll
        for (int ni = 0; ni < 8; ni++)
#pragma unroll
            for (int cc = 0; cc < 4; cc++) acc[mi][ni][cc] = 0.0f;

    issue_chunk(sb, Ah, Al, Bh, Bl, 0, tid);
    CP_COMMIT();

    const int rsel = lane & 15;
    const int kofs = (lane >> 4) * 16;

    for (int k = 0; k < 8; k++) {
        if (k < 7) {
            issue_chunk(sb + ((k + 1) & 1) * STG, Ah, Al, Bh, Bl, k + 1, tid);
            CP_COMMIT();
            CP_WAIT(1);
        } else {
            CP_WAIT(0);
        }
        __syncthreads();

        const uint32_t st = sb + (k & 1) * STG;
#pragma unroll
        for (int ks = 0; ks < 4; ks++) {
            uint32_t ah[2][4], al[2][4], bh[4][4], bl[4][4];
            const uint32_t ko = (uint32_t)(ks * 32 + kofs);
#pragma unroll
            for (int mi = 0; mi < 2; mi++) {
                const uint32_t ra =
                    st + (warp_m * 32 + mi * 16 + rsel) * 144 + ko;
                ldsm4(ah[mi], ra);
                ldsm4(al[mi], ra + MOFS);
            }
#pragma unroll
            for (int ng = 0; ng < 4; ng++) {
                const uint32_t rb =
                    st + 2 * MOFS + (warp_n * 64 + ng * 16 + rsel) * 144 + ko;
                ldsm4(bh[ng], rb);
                ldsm4(bl[ng], rb + MOFS);
            }
#pragma unroll
            for (int mi = 0; mi < 2; mi++)
#pragma unroll
                for (int ni = 0; ni < 8; ni++) {
                    const int ng = ni >> 1, pe = ni & 1;
                    mma_bf16(acc[mi][ni], ah[mi], bh[ng][pe], bh[ng][pe + 2]);
                    mma_bf16(acc[mi][ni], ah[mi], bl[ng][pe], bl[ng][pe + 2]);
                    mma_bf16(acc[mi][ni], al[mi], bh[ng][pe], bh[ng][pe + 2]);
                }
        }
        __syncthreads();
    }

    // ---- epilogue: logits -> exp sums + matched sum (register accumulators)
    const float ls    = *pLS;
    const float curv  = *pCurv;
    const float scale = -ls / sqrtf(curv);
    const bool  fastp = (scale == -10.0f);

    float cxa[4];
    int   la[4], rowl[4];
#pragma unroll
    for (int q = 0; q < 4; q++) {                 // q = mi*2 + half
        const int rl = warp_m * 32 + (q >> 1) * 16 + (lane >> 2) + (q & 1) * 8;
        rowl[q] = rl;
        cxa[q]  = curv * xtA_s[rl];
        la[q]   = labA_s[rl];
    }

    float rs[4], cs[16];
#pragma unroll
    for (int q = 0; q < 4; q++)  rs[q] = 0.0f;
#pragma unroll
    for (int q = 0; q < 16; q++) cs[q] = 0.0f;
    float msum = 0.0f;

#pragma unroll
    for (int mi = 0; mi < 2; mi++)
#pragma unroll
        for (int ni = 0; ni < 8; ni++)
#pragma unroll
            for (int cc = 0; cc < 4; cc++) {
                const int half = cc >> 1, b = cc & 1;
                const int cl = warp_n * 64 + ni * 8 + (lane & 3) * 2 + b;
                const float dot = acc[mi][ni][cc];
                float cv = fmaf(cxa[mi * 2 + half], xtB_s[cl], -curv * dot);
                cv = fmaxf(cv, 1.0f + 1e-8f);
                float e;
                if (fastp && cv >= 64.0f) {
                    const float x2 = 2.0f * cv;
                    float r = __int_as_float(0x7EF311C3u - __float_as_uint(x2));
                    r = r * fmaf(-x2, r, 2.0f);
                    r = r * fmaf(-x2, r, 2.0f);
                    r = r * fmaf(-x2, r, 2.0f);
                    const float r2 = r * r;
                    const float r4 = r2 * r2;
                    const float r8 = r4 * r4;
                    e = (r8 * r2) * fmaf(10.0f, r2, 1.0f);
                } else {
                    const float u = cv + sqrtf(fmaf(cv, cv, -1.0f));
                    e = exp2f(scale * __log2f(u));
                }
                rs[mi * 2 + half] += e;
                cs[ni * 2 + b]    += e;
                if (la[mi * 2 + half] == labB_s[cl]) {
                    const float u = cv + sqrtf(fmaf(cv, cv, -1.0f));
                    msum += __log2f(u);
                }
            }

    // row sums: lanes sharing lane>>2 hold same rows -> reduce within quad
#pragma unroll
    for (int q = 0; q < 4; q++) {
        float v = rs[q];
        v += __shfl_xor_sync(0xffffffffu, v, 1);
        v += __shfl_xor_sync(0xffffffffu, v, 2);
        if ((lane & 3) == 0) atomicAdd(&erow_s[rowl[q]], v);
    }
    // col sums: lanes sharing lane&3 hold same cols -> reduce across lane>>2
#pragma unroll
    for (int q = 0; q < 16; q++) {                // q = ni*2 + b
        float v = cs[q];
        v += __shfl_xor_sync(0xffffffffu, v, 4);
        v += __shfl_xor_sync(0xffffffffu, v, 8);
        v += __shfl_xor_sync(0xffffffffu, v, 16);
        if (lane < 4) {
            const int cl = warp_n * 64 + (q >> 1) * 8 + lane * 2 + (q & 1);
            atomicAdd(&ecol_s[cl], v);
        }
    }
    for (int o = 16; o > 0; o >>= 1)
        msum += __shfl_xor_sync(0xffffffffu, msum, o);
    if (lane == 0) atomicAdd(msum_s, msum);
    __syncthreads();

    if (tid < 128) {
        atomicAdd(&g_se_row[pair][by * 128 + tid], erow_s[tid]);
        atomicAdd(&g_se_col[pair][bx * 128 + tid], ecol_s[tid]);
    }
    if (tid == 0) atomicAdd(&g_matched_t[pair], (double)(*msum_s));
}

// ---------------------------------------------------------------------------
// finalize
// ---------------------------------------------------------------------------
__global__ void __launch_bounds__(256)
finalize_kernel(const float* __restrict__ pLS, const float* __restrict__ pCurv,
                float* __restrict__ out, int out_size) {
    __shared__ double red[256];
    const int tid = threadIdx.x;
    double acc = 0.0;
    for (int i = tid; i < BSZ; i += 256) {
        const double c = (double)g_cnt[i];
        double l = 0.0;
#pragma unroll
        for (int p = 0; p < 3; p++)
            l += (double)logf(g_se_row[p][i]) + (double)logf(g_se_col[p][i]);
        acc += c * l;
    }
    red[tid] = acc;
    __syncthreads();
    for (int o = 128; o > 0; o >>= 1) {
        if (tid < o) red[tid] += red[tid + o];
        __syncthreads();
    }
    if (tid == 0) {
        const double ls       = (double)(*pLS);
        const double curv     = (double)(*pCurv);
        const double scaleLn2 = -(ls / sqrt(curv)) * 0.6931471805599453;
        double matched = 0.0;
        for (int p = 0; p < 3; p++) matched += g_matched_t[p];
        matched *= scaleLn2;
        const double contrast = (red[0] - 2.0 * matched) / (6.0 * (double)BSZ);
        const double entail   = g_acc_entail / (double)BSZ;
        const double total    = contrast + 0.2 * entail;
        if (out_size > 0) out[0] = (float)total;
        if (out_size > 1) out[1] = (float)contrast;
        if (out_size > 2) out[2] = (float)entail;
    }
}

// ---------------------------------------------------------------------------
extern "C" void kernel_launch(void* const* d_in, const int* in_sizes, int n_in,
                              void* d_out, int out_size) {
    const float* img    = (const float*)d_in[0];
    const float* dna    = (const float*)d_in[1];
    const float* txt    = (const float*)d_in[2];
    const int*   labels = (const int*)d_in[3];   // int32 (JAX x64 disabled)
    const float* pLS    = (const float*)d_in[4];
    const float* pCurv  = (const float*)d_in[5];
    float*       out    = (float*)d_out;

    cudaFuncSetAttribute(gemm_ce_wm,
                         cudaFuncAttributeMaxDynamicSharedMemorySize,
                         GEMM_SMEM);

    init_kernel<<<48, 256>>>(labels);
    split_kernel<<<2048, 256>>>(img, 0);
    split_kernel<<<2048, 256>>>(dna, 1);
    split_kernel<<<2048, 256>>>(txt, 2);
    cnt_kernel<<<BSZ / 256, 256>>>();
    time_kernel<<<BSZ, 128>>>(img, pCurv, 0);
    time_kernel<<<BSZ, 128>>>(dna, pCurv, 1);
    time_kernel<<<BSZ, 128>>>(txt, pCurv, 2);
    entail_kernel<<<BSZ, 128>>>(dna, img, pCurv);

    gemm_ce_wm<<<dim3(32, 32, 3), 256, GEMM_SMEM>>>(pLS, pCurv);

    finalize_kernel<<<1, 256>>>(pLS, pCurv, out, out_size);
}

// round 8
// speedup vs baseline: 3.5584x; 2.1744x over previous
#include <cuda_runtime.h>
#include <cuda_bf16.h>
#include <math.h>
#include <stdint.h>

#define BSZ 4096
#define DSZ 512

// ---------------------------------------------------------------------------
// scratch globals (no dynamic allocation anywhere)
// ---------------------------------------------------------------------------
__device__ __align__(16) __nv_bfloat16 g_hi[3][(size_t)BSZ * DSZ];  // 12 MB
__device__ float  g_xt[3][BSZ];
__device__ int    g_lab[BSZ];
__device__ float  g_cnt[BSZ];
__device__ float  g_se_row[3][BSZ];
__device__ float  g_se_col[3][BSZ];
__device__ double g_matched_t[3];
__device__ double g_acc_entail;

// ---------------------------------------------------------------------------
// PTX helpers — baseline ISA only (no sm_103a-gated instructions)
// ---------------------------------------------------------------------------
__device__ __forceinline__ uint32_t smem_u32(const void* p) {
    uint32_t a;
    asm("{ .reg .u64 t; cvta.to.shared.u64 t, %1; cvt.u32.u64 %0, t; }"
        : "=r"(a) : "l"(p));
    return a;
}

__device__ __forceinline__ void cp16(uint32_t s, const void* g) {
    asm volatile("cp.async.cg.shared.global [%0], [%1], 16;"
                 :: "r"(s), "l"(g) : "memory");
}
#define CP_COMMIT() asm volatile("cp.async.commit_group;" ::: "memory")
#define CP_WAIT(n)  asm volatile("cp.async.wait_group %0;" :: "n"(n) : "memory")

__device__ __forceinline__ void ldsm4(uint32_t* r, uint32_t a) {
    asm volatile("ldmatrix.sync.aligned.m8n8.x4.shared.b16 {%0,%1,%2,%3}, [%4];"
                 : "=r"(r[0]), "=r"(r[1]), "=r"(r[2]), "=r"(r[3]) : "r"(a));
}

__device__ __forceinline__ void mma_bf16(float* c, const uint32_t* a,
                                         uint32_t b0, uint32_t b1) {
    asm volatile(
        "mma.sync.aligned.m16n8k16.row.col.f32.bf16.bf16.f32 "
        "{%0,%1,%2,%3}, {%4,%5,%6,%7}, {%8,%9}, {%0,%1,%2,%3};"
        : "+f"(c[0]), "+f"(c[1]), "+f"(c[2]), "+f"(c[3])
        : "r"(a[0]), "r"(a[1]), "r"(a[2]), "r"(a[3]), "r"(b0), "r"(b1));
}

// ---------------------------------------------------------------------------
// initcnt: labels + match counts + zero accumulators (launch #1)
// ---------------------------------------------------------------------------
__global__ void __launch_bounds__(256)
initcnt_kernel(const int* __restrict__ labels) {
    __shared__ int sl[BSZ];
    const int tid = threadIdx.x;
    for (int t = tid; t < BSZ; t += 256) sl[t] = labels[t];
    __syncthreads();
    const int i  = blockIdx.x * 256 + tid;
    const int li = sl[i];
    int c = 0;
#pragma unroll 8
    for (int j = 0; j < BSZ; j++) c += (sl[j] == li) ? 1 : 0;
    g_cnt[i] = (float)c;
    g_lab[i] = li;
#pragma unroll
    for (int p = 0; p < 3; p++) {
        g_se_row[p][i] = 0.0f;
        g_se_col[p][i] = 0.0f;
    }
    if (i < 3)  g_matched_t[i] = 0.0;
    if (i == 0) g_acc_entail = 0.0;
}

// ---------------------------------------------------------------------------
// prep: fused bf16 convert + time component; grid (BSZ, 3) (launch #2)
// ---------------------------------------------------------------------------
__global__ void __launch_bounds__(128)
prep_kernel(const float* __restrict__ img, const float* __restrict__ dna,
            const float* __restrict__ txt, const float* __restrict__ pCurv) {
    __shared__ float red[128];
    const int set = blockIdx.y;
    const float* f = (set == 0) ? img : ((set == 1) ? dna : txt);
    const int i   = blockIdx.x;
    const int tid = threadIdx.x;
    const float4 v = ((const float4*)(f + (size_t)i * DSZ))[tid];

    __nv_bfloat162* dh = (__nv_bfloat162*)(g_hi[set] + (size_t)i * DSZ) + tid * 2;
    dh[0] = __halves2bfloat162(__float2bfloat16(v.x), __float2bfloat16(v.y));
    dh[1] = __halves2bfloat162(__float2bfloat16(v.z), __float2bfloat16(v.w));

    red[tid] = v.x * v.x + v.y * v.y + v.z * v.z + v.w * v.w;
    __syncthreads();
    for (int o = 64; o > 0; o >>= 1) {
        if (tid < o) red[tid] += red[tid + o];
        __syncthreads();
    }
    if (tid == 0) g_xt[set][i] = sqrtf(1.0f / (*pCurv) + red[0]);
}

// ---------------------------------------------------------------------------
// entailment (dna -> image) (launch #3)
// ---------------------------------------------------------------------------
__global__ void entail_kernel(const float* __restrict__ dna,
                              const float* __restrict__ img,
                              const float* __restrict__ pCurv) {
    __shared__ float redd[128];
    __shared__ float redn[128];
    const int i   = blockIdx.x;
    const int tid = threadIdx.x;
    const float4 xv = ((const float4*)(dna + (size_t)i * DSZ))[tid];
    const float4 yv = ((const float4*)(img + (size_t)i * DSZ))[tid];
    redd[tid] = xv.x * yv.x + xv.y * yv.y + xv.z * yv.z + xv.w * yv.w;
    redn[tid] = xv.x * xv.x + xv.y * xv.y + xv.z * xv.z + xv.w * xv.w;
    __syncthreads();
    for (int o = 64; o > 0; o >>= 1) {
        if (tid < o) { redd[tid] += redd[tid + o]; redn[tid] += redn[tid + o]; }
        __syncthreads();
    }
    if (tid == 0) {
        const float curv  = *pCurv;
        const float xt    = g_xt[1][i];
        const float yt    = g_xt[0][i];
        const float dot   = redd[0];
        const float normx = sqrtf(redn[0]);
        const float c     = curv * (dot - xt * yt);
        const float num   = yt + c * xt;
        const float den   = normx * sqrtf(fmaxf(c * c - 1.0f, 0.0f));
        float ain = num / (den + 1e-8f);
        ain = fminf(fmaxf(ain, -1.0f + 1e-8f), 1.0f - 1e-8f);
        const float ang = acosf(ain);
        float asin_in = 0.2f / (normx * sqrtf(curv) + 1e-6f);
        asin_in = fminf(fmaxf(asin_in, -1.0f + 1e-6f), 1.0f - 1e-6f);
        const float ap = asinf(asin_in);
        atomicAdd(&g_acc_entail, (double)fmaxf(ang - ap, 0.0f));
    }
}

// ---------------------------------------------------------------------------
// warp-MMA GEMM (single bf16 term, mma.sync m16n8k16) + fused CE epilogue.
// Tile 128x128, BK=64, double-buffered cp.async, 2 CTAs/SM.
// SMEM: A @0, B @18432 per stage (row stride 144B, conflict-free ldmatrix);
// stage=36864; stage0 @0, stage1 @36864, control @73728.
// ---------------------------------------------------------------------------
#define STG   36864
#define MOFS  18432
#define CTRL  73728
#define GEMM_SMEM (CTRL + 3200)

__device__ __forceinline__ void issue_chunk(
    uint32_t sstage,
    const __nv_bfloat16* __restrict__ Ah, const __nv_bfloat16* __restrict__ Bh,
    int kchunk, int tid)
{
    const int col0 = kchunk * 64;
#pragma unroll
    for (int m = 0; m < 2; m++) {
        const __nv_bfloat16* src = m ? Bh : Ah;
        const uint32_t sm = sstage + m * MOFS;
#pragma unroll
        for (int it = 0; it < 4; it++) {
            const int idx = tid + it * 256;
            const int row = idx >> 3;
            const int seg = idx & 7;
            cp16(sm + row * 144 + seg * 16,
                 src + (size_t)row * DSZ + col0 + seg * 8);
        }
    }
}

__global__ void __launch_bounds__(256, 2)
gemm_ce_wm(int ia, int ib, int pair,
           const float* __restrict__ pLS, const float* __restrict__ pCurv) {
    extern __shared__ char smem[];
    const int tid  = threadIdx.x;
    const int lane = tid & 31;
    const int wid  = tid >> 5;
    const int warp_m = wid & 3;     // 4 row groups of 32
    const int warp_n = wid >> 2;    // 2 col groups of 64
    const int bx = blockIdx.x, by = blockIdx.y;

    const uint32_t sb = smem_u32(smem);

    float* xtA_s  = (float*)(smem + CTRL);
    float* xtB_s  = (float*)(smem + CTRL + 512);
    int*   labA_s = (int*)  (smem + CTRL + 1024);
    int*   labB_s = (int*)  (smem + CTRL + 1536);
    float* erow_s = (float*)(smem + CTRL + 2048);
    float* ecol_s = (float*)(smem + CTRL + 2560);
    float* msum_s = (float*)(smem + CTRL + 3072);

    const __nv_bfloat16* Ah = g_hi[ia] + (size_t)(by * 128) * DSZ;
    const __nv_bfloat16* Bh = g_hi[ib] + (size_t)(bx * 128) * DSZ;

    if (tid < 128) {
        xtA_s[tid]  = g_xt[ia][by * 128 + tid];
        xtB_s[tid]  = g_xt[ib][bx * 128 + tid];
        labA_s[tid] = g_lab[by * 128 + tid];
        labB_s[tid] = g_lab[bx * 128 + tid];
        erow_s[tid] = 0.0f;
        ecol_s[tid] = 0.0f;
    }
    if (tid == 0) *msum_s = 0.0f;

    float acc[2][8][4];
#pragma unroll
    for (int mi = 0; mi < 2; mi++)
#pragma unroll
        for (int ni = 0; ni < 8; ni++)
#pragma unroll
            for (int cc = 0; cc < 4; cc++) acc[mi][ni][cc] = 0.0f;

    issue_chunk(sb, Ah, Bh, 0, tid);
    CP_COMMIT();

    const int rsel = lane & 15;
    const int kofs = (lane >> 4) * 16;

    for (int k = 0; k < 8; k++) {
        if (k < 7) {
            issue_chunk(sb + ((k + 1) & 1) * STG, Ah, Bh, k + 1, tid);
            CP_COMMIT();
            CP_WAIT(1);
        } else {
            CP_WAIT(0);
        }
        __syncthreads();

        const uint32_t st = sb + (k & 1) * STG;
#pragma unroll
        for (int ks = 0; ks < 4; ks++) {
            uint32_t ah[2][4], bh[4][4];
            const uint32_t ko = (uint32_t)(ks * 32 + kofs);
#pragma unroll
            for (int mi = 0; mi < 2; mi++)
                ldsm4(ah[mi], st + (warp_m * 32 + mi * 16 + rsel) * 144 + ko);
#pragma unroll
            for (int ng = 0; ng < 4; ng++)
                ldsm4(bh[ng],
                      st + MOFS + (warp_n * 64 + ng * 16 + rsel) * 144 + ko);
#pragma unroll
            for (int mi = 0; mi < 2; mi++)
#pragma unroll
                for (int ni = 0; ni < 8; ni++) {
                    const int ng = ni >> 1, pe = ni & 1;
                    mma_bf16(acc[mi][ni], ah[mi], bh[ng][pe], bh[ng][pe + 2]);
                }
        }
        __syncthreads();
    }

    // ---- epilogue: logits -> exp sums + matched sum (register accumulators)
    const float ls    = *pLS;
    const float curv  = *pCurv;
    const float scale = -ls / sqrtf(curv);
    const bool  fastp = (scale == -10.0f);

    float cxa[4];
    int   la[4], rowl[4];
#pragma unroll
    for (int q = 0; q < 4; q++) {                 // q = mi*2 + half
        const int rl = warp_m * 32 + (q >> 1) * 16 + (lane >> 2) + (q & 1) * 8;
        rowl[q] = rl;
        cxa[q]  = curv * xtA_s[rl];
        la[q]   = labA_s[rl];
    }

    float rs[4], cs[16];
#pragma unroll
    for (int q = 0; q < 4; q++)  rs[q] = 0.0f;
#pragma unroll
    for (int q = 0; q < 16; q++) cs[q] = 0.0f;
    float msum = 0.0f;

#pragma unroll
    for (int mi = 0; mi < 2; mi++)
#pragma unroll
        for (int ni = 0; ni < 8; ni++)
#pragma unroll
            for (int cc = 0; cc < 4; cc++) {
                const int half = cc >> 1, b = cc & 1;
                const int cl = warp_n * 64 + ni * 8 + (lane & 3) * 2 + b;
                const float dot = acc[mi][ni][cc];
                float cv = fmaf(cxa[mi * 2 + half], xtB_s[cl], -curv * dot);
                cv = fmaxf(cv, 1.0f + 1e-8f);
                float e;
                if (fastp && cv >= 64.0f) {
                    const float x2 = 2.0f * cv;
                    float r = __int_as_float(0x7EF311C3u - __float_as_uint(x2));
                    r = r * fmaf(-x2, r, 2.0f);
                    r = r * fmaf(-x2, r, 2.0f);
                    r = r * fmaf(-x2, r, 2.0f);
                    const float r2 = r * r;
                    const float r4 = r2 * r2;
                    const float r8 = r4 * r4;
                    e = (r8 * r2) * fmaf(10.0f, r2, 1.0f);
                } else {
                    const float u = cv + sqrtf(fmaf(cv, cv, -1.0f));
                    e = exp2f(scale * __log2f(u));
                }
                rs[mi * 2 + half] += e;
                cs[ni * 2 + b]    += e;
                if (la[mi * 2 + half] == labB_s[cl]) {
                    const float u = cv + sqrtf(fmaf(cv, cv, -1.0f));
                    msum += __log2f(u);
                }
            }

    // row sums: lanes sharing lane>>2 hold same rows -> reduce within quad
#pragma unroll
    for (int q = 0; q < 4; q++) {
        float v = rs[q];
        v += __shfl_xor_sync(0xffffffffu, v, 1);
        v += __shfl_xor_sync(0xffffffffu, v, 2);
        if ((lane & 3) == 0) atomicAdd(&erow_s[rowl[q]], v);
    }
    // col sums: lanes sharing lane&3 hold same cols -> reduce across lane>>2
#pragma unroll
    for (int q = 0; q < 16; q++) {                // q = ni*2 + b
        float v = cs[q];
        v += __shfl_xor_sync(0xffffffffu, v, 4);
        v += __shfl_xor_sync(0xffffffffu, v, 8);
        v += __shfl_xor_sync(0xffffffffu, v, 16);
        if (lane < 4) {
            const int cl = warp_n * 64 + (q >> 1) * 8 + lane * 2 + (q & 1);
            atomicAdd(&ecol_s[cl], v);
        }
    }
    for (int o = 16; o > 0; o >>= 1)
        msum += __shfl_xor_sync(0xffffffffu, msum, o);
    if (lane == 0) atomicAdd(msum_s, msum);
    __syncthreads();

    if (tid < 128) {
        atomicAdd(&g_se_row[pair][by * 128 + tid], erow_s[tid]);
        atomicAdd(&g_se_col[pair][bx * 128 + tid], ecol_s[tid]);
    }
    if (tid == 0) atomicAdd(&g_matched_t[pair], (double)(*msum_s));
}

// ---------------------------------------------------------------------------
// finalize
// ---------------------------------------------------------------------------
__global__ void __launch_bounds__(256)
finalize_kernel(const float* __restrict__ pLS, const float* __restrict__ pCurv,
                float* __restrict__ out, int out_size) {
    __shared__ double red[256];
    const int tid = threadIdx.x;
    double acc = 0.0;
    for (int i = tid; i < BSZ; i += 256) {
        const double c = (double)g_cnt[i];
        double l = 0.0;
#pragma unroll
        for (int p = 0; p < 3; p++)
            l += (double)logf(g_se_row[p][i]) + (double)logf(g_se_col[p][i]);
        acc += c * l;
    }
    red[tid] = acc;
    __syncthreads();
    for (int o = 128; o > 0; o >>= 1) {
        if (tid < o) red[tid] += red[tid + o];
        __syncthreads();
    }
    if (tid == 0) {
        const double ls       = (double)(*pLS);
        const double curv     = (double)(*pCurv);
        const double scaleLn2 = -(ls / sqrt(curv)) * 0.6931471805599453;
        double matched = 0.0;
        for (int p = 0; p < 3; p++) matched += g_matched_t[p];
        matched *= scaleLn2;
        const double contrast = (red[0] - 2.0 * matched) / (6.0 * (double)BSZ);
        const double entail   = g_acc_entail / (double)BSZ;
        const double total    = contrast + 0.2 * entail;
        if (out_size > 0) out[0] = (float)total;
        if (out_size > 1) out[1] = (float)contrast;
        if (out_size > 2) out[2] = (float)entail;
    }
}

// ---------------------------------------------------------------------------
extern "C" void kernel_launch(void* const* d_in, const int* in_sizes, int n_in,
                              void* d_out, int out_size) {
    const float* img    = (const float*)d_in[0];
    const float* dna    = (const float*)d_in[1];
    const float* txt    = (const float*)d_in[2];
    const int*   labels = (const int*)d_in[3];   // int32 (JAX x64 disabled)
    const float* pLS    = (const float*)d_in[4];
    const float* pCurv  = (const float*)d_in[5];
    float*       out    = (float*)d_out;

    cudaFuncSetAttribute(gemm_ce_wm,
                         cudaFuncAttributeMaxDynamicSharedMemorySize,
                         GEMM_SMEM);

    initcnt_kernel<<<BSZ / 256, 256>>>(labels);                 // #1
    prep_kernel<<<dim3(BSZ, 3), 128>>>(img, dna, txt, pCurv);   // #2
    entail_kernel<<<BSZ, 128>>>(dna, img, pCurv);               // #3

    const int PA[3] = {0, 0, 1};
    const int PB[3] = {1, 2, 2};
    for (int p = 0; p < 3; p++)                                 // #4, #5, #6
        gemm_ce_wm<<<dim3(32, 32), 256, GEMM_SMEM>>>(PA[p], PB[p], p,
                                                     pLS, pCurv);

    finalize_kernel<<<1, 256>>>(pLS, pCurv, out, out_size);     // #7
}